// round 5
// baseline (speedup 1.0000x reference)
#include <cuda_runtime.h>
#include <cstdint>
#include <cstddef>

// ----------------------------------------------------------------------------
// InstanceSegmentationHead: level assignment + per-level greedy NMS (K=64)
// + ROI align (14x14, 2x2 samples) over 3 feature levels.
// B=2, C=256, N=2048 per source, feature sizes 28/56/112.
// ----------------------------------------------------------------------------

#define NBOX 6144
#define NEGV (-1e30f)
#define BATCH 2
#define CCH 256
#define KKEEP 64
#define OUTP 14
#define CPB 32              // channels per roi block

// ---------------- scratch (__device__ globals; no allocation) ---------------
__device__ unsigned long long g_ckey[6][NBOX];   // packed (ordered_score<<32 | ~orig_idx)
__device__ float4             g_cbox[6][NBOX];   // compacted xyxy (scaled)
__device__ int                g_cnt[6];
__device__ int                g_sel[6][KKEEP];
__device__ float4             g_scaled[BATCH][NBOX]; // cx,cy,w,h (scaled)

// order-preserving float->uint mapping (monotonic)
__device__ __forceinline__ unsigned ford(float f) {
    unsigned u = __float_as_uint(f);
    return (u & 0x80000000u) ? ~u : (u | 0x80000000u);
}

// ---------------------------- stage 0: zero counters -------------------------
__global__ void zero_kernel() {
    if (threadIdx.x < 6) g_cnt[threadIdx.x] = 0;
}

// ------------------- stage 1: prep boxes, levels, compaction -----------------
__global__ void prep_kernel(const float* __restrict__ b32, const float* __restrict__ b16,
                            const float* __restrict__ b8,
                            const float* __restrict__ s32, const float* __restrict__ s16,
                            const float* __restrict__ s8) {
    int i = blockIdx.x * blockDim.x + threadIdx.x;
    if (i >= BATCH * NBOX) return;
    int b = i / NBOX;
    int j = i - b * NBOX;

    const float* bp;
    const float* sp;
    float sc;
    if (j < 2048)      { bp = b32 + ((size_t)b * 2048 + j) * 4;          sp = s32 + (size_t)b * 2048 + j;          sc = 32.f; }
    else if (j < 4096) { int jj = j - 2048; bp = b16 + ((size_t)b * 2048 + jj) * 4; sp = s16 + (size_t)b * 2048 + jj; sc = 16.f; }
    else               { int jj = j - 4096; bp = b8  + ((size_t)b * 2048 + jj) * 4; sp = s8  + (size_t)b * 2048 + jj; sc = 8.f;  }

    float cx = bp[0], cy = bp[1], w = bp[2], h = bp[3];

    // level from UNscaled size: clip(floor(3 + log2(sqrt(w*h)/224)), 1, 4)
    float s  = sqrtf(__fmul_rn(w, h));
    float lv = floorf(__fadd_rn(3.0f, log2f(__fdiv_rn(s, 224.0f))));
    lv = fminf(fmaxf(lv, 1.0f), 4.0f);

    // scaled cxcywh and xyxy (single-op IEEE rounding)
    float scx = __fmul_rn(cx, sc), scy = __fmul_rn(cy, sc);
    float sw  = __fmul_rn(w,  sc), sh  = __fmul_rn(h,  sc);
    g_scaled[b][j] = make_float4(scx, scy, sw, sh);
    float hx = __fmul_rn(sw, 0.5f), hy = __fmul_rn(sh, 0.5f);
    float x1 = __fsub_rn(scx, hx), y1 = __fsub_rn(scy, hy);
    float x2 = __fadd_rn(scx, hx), y2 = __fadd_rn(scy, hy);

    int lvl = (int)lv;
    if (lvl >= 1 && lvl <= 3) {
        int bl  = b * 3 + (lvl - 1);
        int pos = atomicAdd(&g_cnt[bl], 1);
        g_cbox[bl][pos] = make_float4(x1, y1, x2, y2);
        // key: higher score wins; ties -> smaller original index (matches jnp.argmax)
        unsigned long long key =
            ((unsigned long long)ford(*sp) << 32) |
            (unsigned long long)(0xFFFFFFFFu - (unsigned)j);
        g_ckey[bl][pos] = key;
    }
}

// --------------------------- stage 2: greedy NMS -----------------------------
// one block per (batch, level); register-resident; n-bounded scan; one barrier
// per iteration (all warps redundantly reduce the 16 per-warp partials).
#define NMS_BD 512
#define NMS_U  12        // 512*12 = 6144 = NBOX

__global__ void __launch_bounds__(NMS_BD, 1) nms_kernel() {
    extern __shared__ float4 sbox[];             // NBOX float4 (dynamic, 96KB)
    __shared__ unsigned long long rk[16];
    __shared__ int                rp[16];

    int bl  = blockIdx.x;
    int tid = threadIdx.x;
    int lane = tid & 31;
    int n   = g_cnt[bl];

    unsigned long long key[NMS_U];
    float4             box[NMS_U];
    float              area[NMS_U];
    #pragma unroll
    for (int u = 0; u < NMS_U; ++u) {
        key[u]  = 0ull;
        box[u]  = make_float4(0.f, 0.f, 0.f, 0.f);
        area[u] = 0.f;
        if (u * NMS_BD < n) {
            int j = tid + u * NMS_BD;
            unsigned long long k = g_ckey[bl][j];
            float4 bb = g_cbox[bl][j];
            sbox[j] = bb;
            box[u]  = bb;
            area[u] = __fmul_rn(fmaxf(__fsub_rn(bb.z, bb.x), 0.f),
                                fmaxf(__fsub_rn(bb.w, bb.y), 0.f));
            key[u]  = (j < n) ? k : 0ull;       // 0 never wins / never passes threshold
        }
    }
    __syncthreads();

    const unsigned long long KTHRESH = ((unsigned long long)ford(-5e29f)) << 32; // NEG/2
    const unsigned long long FNEGHI  = ((unsigned long long)ford(NEGV)) << 32;
    const float MLO = 2.9802322387695312e-8f;    // 2^-25 = half-ulp of 0.7f

    // initial "winner" suppresses nothing (intersection clamps to 0)
    float4 wb = make_float4(1e30f, 1e30f, 1e30f, 1e30f);

    int it = 0;
    for (; it < KKEEP; ++it) {
        float a = __fmul_rn(fmaxf(__fsub_rn(wb.z, wb.x), 0.f),
                            fmaxf(__fsub_rn(wb.w, wb.y), 0.f));

        unsigned long long bk = 0ull;
        int bp = 0;

        #pragma unroll
        for (int u = 0; u < NMS_U; ++u) {
            if (u * NMS_BD >= n) break;          // uniform: skip unused tail
            float4 bb = box[u];
            float ix1 = fmaxf(wb.x, bb.x), iy1 = fmaxf(wb.y, bb.y);
            float ix2 = fminf(wb.z, bb.z), iy2 = fminf(wb.w, bb.w);
            float inter = __fmul_rn(fmaxf(__fsub_rn(ix2, ix1), 0.f),
                                    fmaxf(__fsub_rn(iy2, iy1), 0.f));
            float denom = __fadd_rn(__fsub_rn(__fadd_rn(a, area[u]), inter), 1e-9f);
            // suppress  <=>  rn(inter/denom) > 0.7f  <=>  inter >= (0.7f + 2^-25)*denom
            float dd = __fmaf_rn(-0.7f, denom, inter);
            float tt = __fmul_rn(MLO, denom);    // exact (power of two)
            if (dd >= tt)
                key[u] = FNEGHI | (key[u] & 0xFFFFFFFFull);
            if (key[u] > bk) { bk = key[u]; bp = tid + u * NMS_BD; }
        }

        // warp-level argmax of (key, pos)
        #pragma unroll
        for (int off = 16; off; off >>= 1) {
            unsigned long long ok = __shfl_down_sync(0xFFFFFFFFu, bk, off);
            int                op = __shfl_down_sync(0xFFFFFFFFu, bp, off);
            if (ok > bk) { bk = ok; bp = op; }
        }
        if (lane == 0) { rk[tid >> 5] = bk; rp[tid >> 5] = bp; }
        __syncthreads();

        // every warp reduces the 16 partials (no second barrier needed)
        bk = (lane < 16) ? rk[lane] : 0ull;
        bp = (lane < 16) ? rp[lane] : 0;
        #pragma unroll
        for (int off = 8; off; off >>= 1) {
            unsigned long long ok = __shfl_down_sync(0xFFFFFFFFu, bk, off);
            int                op = __shfl_down_sync(0xFFFFFFFFu, bp, off);
            if (ok > bk) { bk = ok; bp = op; }
        }
        bk = __shfl_sync(0xFFFFFFFFu, bk, 0);
        bp = __shfl_sync(0xFFFFFFFFu, bp, 0);

        if (bk <= KTHRESH) break;               // best score <= NEG/2 -> rest are -1
        wb = sbox[bp];                          // same addr all lanes: broadcast
        if (tid == 0)
            g_sel[bl][it] = (int)(0xFFFFFFFFu - (unsigned)(bk & 0xFFFFFFFFull));
        // NOTE: next iteration's __syncthreads orders key[] updates vs rk reads
    }

    for (int j = it + tid; j < KKEEP; j += NMS_BD) g_sel[bl][j] = -1;
}

// ---------------------------- stage 3: ROI align -----------------------------
// grid.x = B*192 (one (b,k)), grid.y = 8 channel groups of CPB=32. 256 threads.
// Fast path: box fully right/below the map -> tile == F[c][S*S-1] exactly.
// Slow path: stage the 56x56 sample-grid gather in SMEM per channel
// (double-buffered), then 196 pixel threads do 16 LDS+FMA per channel.
__global__ void __launch_bounds__(256, 3) roi_kernel(const float* __restrict__ p32,
                                                     const float* __restrict__ p16,
                                                     const float* __restrict__ p8,
                                                     float* __restrict__ out) {
    __shared__ float G[2][56 * 56];          // 25088 B
    __shared__ int   sYrow[56], sXcol[56];   // premultiplied row offset / col idx
    __shared__ float sfy[28], sfx[28];

    int bk  = blockIdx.x;          // 0..383
    int b   = bk / 192;
    int k   = bk - b * 192;
    int lvl = k >> 6;              // 0,1,2
    int kk  = k & 63;
    int cg  = blockIdx.y * CPB;
    int tid = threadIdx.x;

    float* o = out + (size_t)bk * (CCH * OUTP * OUTP) + (size_t)cg * (OUTP * OUTP);
    float4* o4 = (float4*)o;       // 784B-aligned

    int sel = g_sel[b * 3 + lvl][kk];
    if (sel < 0) {
        float4 z = make_float4(0.f, 0.f, 0.f, 0.f);
        for (int i = tid; i < CPB * 49; i += 256) o4[i] = z;
        return;
    }

    int S = (lvl == 0) ? 28 : (lvl == 1) ? 56 : 112;
    int SS = S * S;
    const float* fbase = ((lvl == 0) ? p32 : (lvl == 1) ? p16 : p8)
                         + ((size_t)b * CCH + cg) * (size_t)SS;

    // NOTE: reference feeds scaled cx,cy,w,h into roi_align as x1,y1,x2,y2
    float4 box = g_scaled[b][sel];
    float x1 = box.x, y1 = box.y, x2 = box.z, y2 = box.w;
    float bw = __fdiv_rn(__fsub_rn(x2, x1), 14.0f);
    float bh = __fdiv_rn(__fsub_rn(y2, y1), 14.0f);

    // fast path: all samples clamp to the (S-1,S-1) corner
    if (x1 >= (float)(S - 1) && y1 >= (float)(S - 1) && bw >= 0.f && bh >= 0.f) {
        int c = tid >> 3, r = tid & 7;
        if (r < 7) {
            float v = __ldg(fbase + (size_t)c * SS + (SS - 1));
            float4 v4 = make_float4(v, v, v, v);
            int base = c * 49 + r * 7;
            #pragma unroll
            for (int j = 0; j < 7; ++j) o4[base + j] = v4;
        }
        return;
    }

    // ---- slow path: build sample tables (28 x-samples, 28 y-samples) ----
    if (tid < 56) {
        int j = (tid < 28) ? tid : tid - 28;
        float t = __fadd_rn((float)(j >> 1), (j & 1) ? 0.75f : 0.25f);
        float lim = (float)(S - 1);
        if (tid < 28) {
            float cx = __fadd_rn(x1, __fmul_rn(t, bw));
            cx = fminf(fmaxf(cx, 0.0f), lim);
            float c0 = floorf(cx);
            sfx[j] = __fsub_rn(cx, c0);
            int i0 = (int)c0;
            sXcol[2 * j]     = i0;
            sXcol[2 * j + 1] = min(i0 + 1, S - 1);
        } else {
            float cy = __fadd_rn(y1, __fmul_rn(t, bh));
            cy = fminf(fmaxf(cy, 0.0f), lim);
            float c0 = floorf(cy);
            sfy[j] = __fsub_rn(cy, c0);
            int i0 = (int)c0;
            sYrow[2 * j]     = i0 * S;                 // premultiplied
            sYrow[2 * j + 1] = min(i0 + 1, S - 1) * S;
        }
    }
    __syncthreads();

    // ---- per-pixel smem offsets + weights (0.25 mean folded in) ----
    int   Og[16];
    float Wg[16];
    int p = tid;
    if (p < OUTP * OUTP) {
        int oy = p / OUTP;
        int ox = p - oy * OUTP;
        #pragma unroll
        for (int sy = 0; sy < 2; ++sy) {
            int yi = 2 * oy + sy;
            float gy = sfy[yi], igy = 1.0f - gy;
            #pragma unroll
            for (int sx = 0; sx < 2; ++sx) {
                int xi = 2 * ox + sx;
                float gx = sfx[xi], igx = 1.0f - gx;
                int s4 = (sy * 2 + sx) * 4;
                int rb0 = (2 * yi) * 56, rb1 = (2 * yi + 1) * 56;
                int cb0 = 2 * xi, cb1 = 2 * xi + 1;
                Og[s4 + 0] = rb0 + cb0;  Wg[s4 + 0] = igy * igx * 0.25f;
                Og[s4 + 1] = rb0 + cb1;  Wg[s4 + 1] = igy * gx  * 0.25f;
                Og[s4 + 2] = rb1 + cb0;  Wg[s4 + 2] = gy  * igx * 0.25f;
                Og[s4 + 3] = rb1 + cb1;  Wg[s4 + 3] = gy  * gx  * 0.25f;
            }
        }
    }

    // ---- channel loop, double-buffered gather ----
    // fill buffer 0 with channel 0
    {
        const float* f = fbase;
        for (int e = tid; e < 56 * 56; e += 256) {
            unsigned a = (unsigned)e / 56u;
            unsigned bb = (unsigned)e - a * 56u;
            G[0][e] = __ldg(f + sYrow[a] + sXcol[bb]);
        }
    }
    __syncthreads();

    for (int c = 0; c < CPB; ++c) {
        int cur = c & 1;
        if (c + 1 < CPB) {
            const float* f = fbase + (size_t)(c + 1) * SS;
            for (int e = tid; e < 56 * 56; e += 256) {
                unsigned a = (unsigned)e / 56u;
                unsigned bb = (unsigned)e - a * 56u;
                G[cur ^ 1][e] = __ldg(f + sYrow[a] + sXcol[bb]);
            }
        }
        if (p < OUTP * OUTP) {
            const float* Gc = G[cur];
            float a0 = 0.f, a1 = 0.f, a2 = 0.f, a3 = 0.f;
            #pragma unroll
            for (int i = 0; i < 4; ++i) {
                a0 = fmaf(Gc[Og[4 * i + 0]], Wg[4 * i + 0], a0);
                a1 = fmaf(Gc[Og[4 * i + 1]], Wg[4 * i + 1], a1);
                a2 = fmaf(Gc[Og[4 * i + 2]], Wg[4 * i + 2], a2);
                a3 = fmaf(Gc[Og[4 * i + 3]], Wg[4 * i + 3], a3);
            }
            o[c * (OUTP * OUTP) + p] = (a0 + a1) + (a2 + a3);
        }
        __syncthreads();
    }
}

// ------------------------------- launcher ------------------------------------
extern "C" void kernel_launch(void* const* d_in, const int* in_sizes, int n_in,
                              void* d_out, int out_size) {
    const float* p32 = (const float*)d_in[0];
    const float* p16 = (const float*)d_in[1];
    const float* p8  = (const float*)d_in[2];
    // d_in[3] = p4 (unused by the reference forward)
    const float* b32 = (const float*)d_in[4];
    const float* b16 = (const float*)d_in[5];
    const float* b8  = (const float*)d_in[6];
    const float* s32 = (const float*)d_in[7];
    const float* s16 = (const float*)d_in[8];
    const float* s8  = (const float*)d_in[9];
    float* out = (float*)d_out;

    static const size_t NMS_SMEM = (size_t)NBOX * sizeof(float4);   // 96KB
    cudaFuncSetAttribute(nms_kernel, cudaFuncAttributeMaxDynamicSharedMemorySize,
                         (int)NMS_SMEM);

    zero_kernel<<<1, 32>>>();
    prep_kernel<<<(BATCH * NBOX + 255) / 256, 256>>>(b32, b16, b8, s32, s16, s8);
    nms_kernel<<<6, NMS_BD, NMS_SMEM>>>();

    dim3 rg(BATCH * 192, CCH / CPB);
    roi_kernel<<<rg, 256>>>(p32, p16, p8, out);
}

// round 6
// speedup vs baseline: 1.6070x; 1.6070x over previous
#include <cuda_runtime.h>
#include <cstdint>
#include <cstddef>

// ----------------------------------------------------------------------------
// InstanceSegmentationHead: level assignment + per-level greedy NMS (K=64)
// + ROI align (14x14, 2x2 samples) over 3 feature levels.
// B=2, C=256, N=2048 per source, feature sizes 28/56/112.
// ----------------------------------------------------------------------------

#define NBOX 6144
#define NEGV (-1e30f)
#define BATCH 2
#define CCH 256
#define KKEEP 64
#define OUTP 14
#define CPB 16              // channels per roi block

// ---------------- scratch (__device__ globals; no allocation) ---------------
__device__ unsigned long long g_ckey[6][NBOX];   // packed (ordered_score<<32 | ~orig_idx)
__device__ float4             g_cbox[6][NBOX];   // compacted xyxy (scaled)
__device__ int                g_cnt[6];
__device__ int                g_sel[6][KKEEP];
__device__ float4             g_scaled[BATCH][NBOX]; // cx,cy,w,h (scaled)

// order-preserving float->uint mapping (monotonic)
__device__ __forceinline__ unsigned ford(float f) {
    unsigned u = __float_as_uint(f);
    return (u & 0x80000000u) ? ~u : (u | 0x80000000u);
}

// ---------------------------- stage 0: zero counters -------------------------
__global__ void zero_kernel() {
    if (threadIdx.x < 6) g_cnt[threadIdx.x] = 0;
}

// ------------------- stage 1: prep boxes, levels, compaction -----------------
__global__ void prep_kernel(const float* __restrict__ b32, const float* __restrict__ b16,
                            const float* __restrict__ b8,
                            const float* __restrict__ s32, const float* __restrict__ s16,
                            const float* __restrict__ s8) {
    int i = blockIdx.x * blockDim.x + threadIdx.x;
    if (i >= BATCH * NBOX) return;
    int b = i / NBOX;
    int j = i - b * NBOX;

    const float* bp;
    const float* sp;
    float sc;
    if (j < 2048)      { bp = b32 + ((size_t)b * 2048 + j) * 4;          sp = s32 + (size_t)b * 2048 + j;          sc = 32.f; }
    else if (j < 4096) { int jj = j - 2048; bp = b16 + ((size_t)b * 2048 + jj) * 4; sp = s16 + (size_t)b * 2048 + jj; sc = 16.f; }
    else               { int jj = j - 4096; bp = b8  + ((size_t)b * 2048 + jj) * 4; sp = s8  + (size_t)b * 2048 + jj; sc = 8.f;  }

    float cx = bp[0], cy = bp[1], w = bp[2], h = bp[3];

    // level from UNscaled size: clip(floor(3 + log2(sqrt(w*h)/224)), 1, 4)
    float s  = sqrtf(__fmul_rn(w, h));
    float lv = floorf(__fadd_rn(3.0f, log2f(__fdiv_rn(s, 224.0f))));
    lv = fminf(fmaxf(lv, 1.0f), 4.0f);

    // scaled cxcywh and xyxy (single-op IEEE rounding)
    float scx = __fmul_rn(cx, sc), scy = __fmul_rn(cy, sc);
    float sw  = __fmul_rn(w,  sc), sh  = __fmul_rn(h,  sc);
    g_scaled[b][j] = make_float4(scx, scy, sw, sh);
    float hx = __fmul_rn(sw, 0.5f), hy = __fmul_rn(sh, 0.5f);
    float x1 = __fsub_rn(scx, hx), y1 = __fsub_rn(scy, hy);
    float x2 = __fadd_rn(scx, hx), y2 = __fadd_rn(scy, hy);

    int lvl = (int)lv;
    if (lvl >= 1 && lvl <= 3) {
        int bl  = b * 3 + (lvl - 1);
        int pos = atomicAdd(&g_cnt[bl], 1);
        g_cbox[bl][pos] = make_float4(x1, y1, x2, y2);
        // key: higher score wins; ties -> smaller original index (matches jnp.argmax)
        unsigned long long key =
            ((unsigned long long)ford(*sp) << 32) |
            (unsigned long long)(0xFFFFFFFFu - (unsigned)j);
        g_ckey[bl][pos] = key;
    }
}

// --------------------------- stage 2: greedy NMS -----------------------------
// one block per (batch, level); register-resident; n-bounded scan;
// division-free IoU threshold (exactly equivalent to rn(inter/denom) > 0.7f).
#define NMS_BD 512
#define NMS_U  12        // 512*12 = 6144 = NBOX

__global__ void __launch_bounds__(NMS_BD, 1) nms_kernel() {
    extern __shared__ float4 sbox[];             // NBOX float4 (dynamic, 96KB)
    __shared__ unsigned long long rk[16];
    __shared__ int                rp[16];
    __shared__ unsigned long long s_wk;
    __shared__ float4             s_wb;

    int bl  = blockIdx.x;
    int tid = threadIdx.x;
    int n   = g_cnt[bl];

    unsigned long long key[NMS_U];
    float4             box[NMS_U];
    float              area[NMS_U];
    #pragma unroll
    for (int u = 0; u < NMS_U; ++u) {
        key[u]  = 0ull;
        box[u]  = make_float4(0.f, 0.f, 0.f, 0.f);
        area[u] = 0.f;
        if (u * NMS_BD < n) {
            int j = tid + u * NMS_BD;
            unsigned long long k = g_ckey[bl][j];
            float4 bb = g_cbox[bl][j];
            sbox[j] = bb;
            box[u]  = bb;
            area[u] = __fmul_rn(fmaxf(__fsub_rn(bb.z, bb.x), 0.f),
                                fmaxf(__fsub_rn(bb.w, bb.y), 0.f));
            key[u]  = (j < n) ? k : 0ull;       // 0 never wins / never passes threshold
        }
    }
    __syncthreads();

    const unsigned long long KTHRESH = ((unsigned long long)ford(-5e29f)) << 32; // NEG/2
    const unsigned long long FNEGHI  = ((unsigned long long)ford(NEGV)) << 32;
    const float MLO = 2.9802322387695312e-8f;    // 2^-25 = half-ulp of 0.7f

    // initial "winner" suppresses nothing (intersection clamps to 0)
    float4 wb = make_float4(1e30f, 1e30f, 1e30f, 1e30f);

    int it = 0;
    for (; it < KKEEP; ++it) {
        float a = __fmul_rn(fmaxf(__fsub_rn(wb.z, wb.x), 0.f),
                            fmaxf(__fsub_rn(wb.w, wb.y), 0.f));

        unsigned long long bk = 0ull;
        int bp = 0;

        #pragma unroll
        for (int u = 0; u < NMS_U; ++u) {
            if (u * NMS_BD >= n) break;          // uniform: skip unused tail
            float4 bb = box[u];
            float ix1 = fmaxf(wb.x, bb.x), iy1 = fmaxf(wb.y, bb.y);
            float ix2 = fminf(wb.z, bb.z), iy2 = fminf(wb.w, bb.w);
            float inter = __fmul_rn(fmaxf(__fsub_rn(ix2, ix1), 0.f),
                                    fmaxf(__fsub_rn(iy2, iy1), 0.f));
            float denom = __fadd_rn(__fsub_rn(__fadd_rn(a, area[u]), inter), 1e-9f);
            // suppress  <=>  rn(inter/denom) > 0.7f  <=>  inter >= (0.7f + 2^-25)*denom
            float dd = __fmaf_rn(-0.7f, denom, inter);
            float tt = __fmul_rn(MLO, denom);    // exact (power of two)
            if (dd >= tt)
                key[u] = FNEGHI | (key[u] & 0xFFFFFFFFull);
            if (key[u] > bk) { bk = key[u]; bp = tid + u * NMS_BD; }
        }

        // block argmax of (key, pos)
        #pragma unroll
        for (int off = 16; off; off >>= 1) {
            unsigned long long ok = __shfl_down_sync(0xFFFFFFFFu, bk, off);
            int                op = __shfl_down_sync(0xFFFFFFFFu, bp, off);
            if (ok > bk) { bk = ok; bp = op; }
        }
        if ((tid & 31) == 0) { rk[tid >> 5] = bk; rp[tid >> 5] = bp; }
        __syncthreads();
        if (tid < 32) {
            bk = (tid < 16) ? rk[tid] : 0ull;
            bp = (tid < 16) ? rp[tid] : 0;
            #pragma unroll
            for (int off = 8; off; off >>= 1) {
                unsigned long long ok = __shfl_down_sync(0xFFFFFFFFu, bk, off);
                int                op = __shfl_down_sync(0xFFFFFFFFu, bp, off);
                if (ok > bk) { bk = ok; bp = op; }
            }
            if (tid == 0) { s_wk = bk; s_wb = sbox[bp]; }
        }
        __syncthreads();

        unsigned long long wk = s_wk;
        if (wk <= KTHRESH) break;               // best score <= NEG/2 -> rest are -1
        wb = s_wb;
        if (tid == 0)
            g_sel[bl][it] = (int)(0xFFFFFFFFu - (unsigned)(wk & 0xFFFFFFFFull));
    }

    for (int j = it + tid; j < KKEEP; j += NMS_BD) g_sel[bl][j] = -1;
}

// ---------------------------- stage 3: ROI align -----------------------------
// grid.x = B*192 (one (b,k)), grid.y = 16 channel groups of CPB=16. 224 threads.
// Fast path: box fully right/below the map -> tile == F[c][S*S-1] exactly
// (weights are exactly {1,0,0,0}; mean of 4 equal values is exact).
__global__ void __launch_bounds__(224, 4) roi_kernel(const float* __restrict__ p32,
                                                     const float* __restrict__ p16,
                                                     const float* __restrict__ p8,
                                                     float* __restrict__ out) {
    int bk  = blockIdx.x;          // 0..383
    int b   = bk / 192;
    int k   = bk - b * 192;
    int lvl = k >> 6;              // 0,1,2
    int kk  = k & 63;
    int cg  = blockIdx.y * CPB;
    int tid = threadIdx.x;

    float* o = out + (size_t)bk * (CCH * OUTP * OUTP) + (size_t)cg * (OUTP * OUTP);
    float4* o4 = (float4*)o;       // 784B-aligned

    int sel = g_sel[b * 3 + lvl][kk];
    if (sel < 0) {
        float4 z = make_float4(0.f, 0.f, 0.f, 0.f);
        for (int i = tid; i < CPB * 49; i += 224) o4[i] = z;
        return;
    }

    int S = (lvl == 0) ? 28 : (lvl == 1) ? 56 : 112;
    int SS = S * S;
    const float* fbase = ((lvl == 0) ? p32 : (lvl == 1) ? p16 : p8)
                         + ((size_t)b * CCH + cg) * (size_t)SS;

    // NOTE: reference feeds scaled cx,cy,w,h into roi_align as x1,y1,x2,y2
    float4 box = g_scaled[b][sel];
    float x1 = box.x, y1 = box.y, x2 = box.z, y2 = box.w;
    float bw = __fdiv_rn(__fsub_rn(x2, x1), 14.0f);
    float bh = __fdiv_rn(__fsub_rn(y2, y1), 14.0f);

    // fast path: all samples clamp to the (S-1,S-1) corner.
    // 224 = CPB(16) * 14 -> full coverage: c in [0,16), r in [0,14)
    if (x1 >= (float)(S - 1) && y1 >= (float)(S - 1) && bw >= 0.f && bh >= 0.f) {
        int c = tid / 14;
        int r = tid - c * 14;
        float v = __ldg(fbase + (size_t)c * SS + (SS - 1));
        float4 v4 = make_float4(v, v, v, v);
        int base = c * 49;
        #pragma unroll
        for (int i = r; i < 49; i += 14) o4[base + i] = v4;
        return;
    }

    if (tid >= OUTP * OUTP) return;             // 196 active threads

    int p  = tid;
    int oy = p / OUTP;
    int ox = p - oy * OUTP;
    float lim = (float)(S - 1);

    int   iy0[2], iy1[2], ix0[2], ix1[2];
    float fy[2], fx[2];
    #pragma unroll
    for (int s = 0; s < 2; ++s) {
        float ty = __fadd_rn((float)oy, s ? 0.75f : 0.25f);
        float cy = __fadd_rn(y1, __fmul_rn(ty, bh));
        cy = fminf(fmaxf(cy, 0.0f), lim);
        float c0 = floorf(cy);
        fy[s]  = __fsub_rn(cy, c0);
        iy0[s] = (int)c0;
        iy1[s] = min(iy0[s] + 1, S - 1);

        float tx = __fadd_rn((float)ox, s ? 0.75f : 0.25f);
        float cx = __fadd_rn(x1, __fmul_rn(tx, bw));
        cx = fminf(fmaxf(cx, 0.0f), lim);
        float d0 = floorf(cx);
        fx[s]  = __fsub_rn(cx, d0);
        ix0[s] = (int)d0;
        ix1[s] = min(ix0[s] + 1, S - 1);
    }

    // 16 corner offsets + weights (0.25 mean folded in)
    int   off[16];
    float w[16];
    #pragma unroll
    for (int sy = 0; sy < 2; ++sy) {
        #pragma unroll
        for (int sx = 0; sx < 2; ++sx) {
            int s4 = (sy * 2 + sx) * 4;
            int Y0 = iy0[sy] * S, Y1 = iy1[sy] * S;
            float gy = fy[sy], igy = 1.0f - gy;
            float gx = fx[sx], igx = 1.0f - gx;
            off[s4 + 0] = Y0 + ix0[sx];  w[s4 + 0] = igy * igx * 0.25f;
            off[s4 + 1] = Y0 + ix1[sx];  w[s4 + 1] = igy * gx  * 0.25f;
            off[s4 + 2] = Y1 + ix0[sx];  w[s4 + 2] = gy  * igx * 0.25f;
            off[s4 + 3] = Y1 + ix1[sx];  w[s4 + 3] = gy  * gx  * 0.25f;
        }
    }

    const float* f  = fbase;
    float*       op = o + p;
    #pragma unroll 2
    for (int c = 0; c < CPB; ++c) {
        float a0 = 0.f, a1 = 0.f, a2 = 0.f, a3 = 0.f;
        #pragma unroll
        for (int i = 0; i < 4; ++i) {
            a0 = fmaf(__ldg(f + off[4 * i + 0]), w[4 * i + 0], a0);
            a1 = fmaf(__ldg(f + off[4 * i + 1]), w[4 * i + 1], a1);
            a2 = fmaf(__ldg(f + off[4 * i + 2]), w[4 * i + 2], a2);
            a3 = fmaf(__ldg(f + off[4 * i + 3]), w[4 * i + 3], a3);
        }
        *op = (a0 + a1) + (a2 + a3);
        f  += SS;
        op += OUTP * OUTP;
    }
}

// ------------------------------- launcher ------------------------------------
extern "C" void kernel_launch(void* const* d_in, const int* in_sizes, int n_in,
                              void* d_out, int out_size) {
    const float* p32 = (const float*)d_in[0];
    const float* p16 = (const float*)d_in[1];
    const float* p8  = (const float*)d_in[2];
    // d_in[3] = p4 (unused by the reference forward)
    const float* b32 = (const float*)d_in[4];
    const float* b16 = (const float*)d_in[5];
    const float* b8  = (const float*)d_in[6];
    const float* s32 = (const float*)d_in[7];
    const float* s16 = (const float*)d_in[8];
    const float* s8  = (const float*)d_in[9];
    float* out = (float*)d_out;

    static const size_t NMS_SMEM = (size_t)NBOX * sizeof(float4);   // 96KB
    cudaFuncSetAttribute(nms_kernel, cudaFuncAttributeMaxDynamicSharedMemorySize,
                         (int)NMS_SMEM);

    zero_kernel<<<1, 32>>>();
    prep_kernel<<<(BATCH * NBOX + 255) / 256, 256>>>(b32, b16, b8, s32, s16, s8);
    nms_kernel<<<6, NMS_BD, NMS_SMEM>>>();

    dim3 rg(BATCH * 192, CCH / CPB);
    roi_kernel<<<rg, 224>>>(p32, p16, p8, out);
}